// round 16
// baseline (speedup 1.0000x reference)
#include <cuda_runtime.h>
#include <cuda_bf16.h>
#include <math.h>
#include <stdint.h>

#define BB   16
#define LL   2048
#define HH   256
#define NN   64
#define NLAY 4
#define IND  40
#define OUTD 33
#define TB   64
#define NBLK 32
#define LH   (NLAY * HH)

typedef unsigned long long ull;

__device__ float g_h [BB * LL * HH];
__device__ float g_zt[BB * HH * LL];
__device__ float g_yt[BB * HH * LL];
__device__ float g_ar [LH * NN], g_ai [LH * NN];
__device__ float g_w2r[LH * NN], g_w2i[LH * NN];
__device__ float g_aTr[LH * NN], g_aTi[LH * NN];
__device__ float g_pr [LH * TB * NN], g_pi [LH * TB * NN];
__device__ float g_kv [LH * TB];
__device__ uint32_t g_bl[LH * 64 * 192];   // tf32 B for GEMM1 [lh][k=64][n=192]
__device__ uint32_t g_bc[LH * 128 * 64];   // tf32 B for GEMM2 [lh][k=128][t=64]

__device__ __forceinline__ float gelu1(float x) {
    const float c0 = 0.7978845608028654f, c1 = 0.044715f;
    float t = tanhf(c0 * (x + c1 * x * x * x));
    return 0.5f * x * (1.0f + t);
}
__device__ __forceinline__ uint32_t f2tf32(float x) {
    uint32_t r; asm("cvt.rna.tf32.f32 %0, %1;" : "=r"(r) : "f"(x)); return r;
}
__device__ __forceinline__ void mma_tf32(float c[4], uint32_t a0, uint32_t a1,
                                         uint32_t a2, uint32_t a3,
                                         uint32_t b0, uint32_t b1) {
    asm volatile("mma.sync.aligned.m16n8k8.row.col.f32.tf32.tf32.f32 "
        "{%0,%1,%2,%3}, {%4,%5,%6,%7}, {%8,%9}, {%0,%1,%2,%3};"
        : "+f"(c[0]), "+f"(c[1]), "+f"(c[2]), "+f"(c[3])
        : "r"(a0), "r"(a1), "r"(a2), "r"(a3), "r"(b0), "r"(b1));
}

__global__ void enc_kernel(const float* __restrict__ x,
                           const float* __restrict__ ew,
                           const float* __restrict__ eb) {
    __shared__ float sw[IND * HH];
    __shared__ float sx[16 * IND];
    int tid = threadIdx.x;
    for (int idx = tid; idx < HH * IND; idx += 256) {
        int h = idx / IND, i = idx % IND;
        sw[i * HH + h] = ew[idx];
    }
    int m0 = blockIdx.x * 16;
    for (int idx = tid; idx < 16 * IND; idx += 256)
        sx[idx] = x[(size_t)m0 * IND + idx];
    __syncthreads();
    float bias = eb[tid];
    for (int r = 0; r < 16; ++r) {
        float acc = bias;
        #pragma unroll
        for (int i = 0; i < IND; ++i)
            acc = fmaf(sx[r * IND + i], sw[i * HH + tid], acc);
        g_h[(size_t)(m0 + r) * HH + tid] = acc;
    }
}

__global__ void ln_kernel(const float* __restrict__ sc,
                          const float* __restrict__ bi) {
    __shared__ float sm[32][257];
    int tid  = threadIdx.x;
    int warp = tid >> 5;
    int lane = tid & 31;
    int m0 = blockIdx.x * 32;
    for (int r = warp; r < 32; r += 8) {
        const float* row = g_h + (size_t)(m0 + r) * HH;
        float4 v0 = *reinterpret_cast<const float4*>(row + lane * 4);
        float4 v1 = *reinterpret_cast<const float4*>(row + 128 + lane * 4);
        float s = v0.x + v0.y + v0.z + v0.w + v1.x + v1.y + v1.z + v1.w;
        float q = v0.x*v0.x + v0.y*v0.y + v0.z*v0.z + v0.w*v0.w
                + v1.x*v1.x + v1.y*v1.y + v1.z*v1.z + v1.w*v1.w;
        #pragma unroll
        for (int m = 16; m; m >>= 1) {
            s += __shfl_xor_sync(0xffffffffu, s, m);
            q += __shfl_xor_sync(0xffffffffu, q, m);
        }
        float mu  = s * (1.0f / 256.0f);
        float var = q * (1.0f / 256.0f) - mu * mu;
        float inv = rsqrtf(var + 1e-5f);
        int h0 = lane * 4, h1 = 128 + lane * 4;
        sm[r][h0+0] = (v0.x - mu) * inv * sc[h0+0] + bi[h0+0];
        sm[r][h0+1] = (v0.y - mu) * inv * sc[h0+1] + bi[h0+1];
        sm[r][h0+2] = (v0.z - mu) * inv * sc[h0+2] + bi[h0+2];
        sm[r][h0+3] = (v0.w - mu) * inv * sc[h0+3] + bi[h0+3];
        sm[r][h1+0] = (v1.x - mu) * inv * sc[h1+0] + bi[h1+0];
        sm[r][h1+1] = (v1.y - mu) * inv * sc[h1+1] + bi[h1+1];
        sm[r][h1+2] = (v1.z - mu) * inv * sc[h1+2] + bi[h1+2];
        sm[r][h1+3] = (v1.w - mu) * inv * sc[h1+3] + bi[h1+3];
    }
    __syncthreads();
    int b  = m0 >> 11;
    int l0 = m0 & 2047;
    for (int h = warp; h < HH; h += 8)
        g_zt[((size_t)(b * HH + h)) * LL + l0 + lane] = sm[lane][h];
}

// ------------------------------------------------------------------
// Batched (all-layer) parameter pipeline
// ------------------------------------------------------------------
__global__ void ssm_prep(const float* __restrict__ lre,
                         const float* __restrict__ lim,
                         const float* __restrict__ cre,
                         const float* __restrict__ cim,
                         const float* __restrict__ lstep) {
    int idx = blockIdx.x * blockDim.x + threadIdx.x;   // over LH*NN
    int lh = idx >> 6;
    float Lre = lre[idx], Lim = lim[idx];
    float Cre = cre[idx], Cim = cim[idx];
    float dt  = expf(lstep[lh]);
    float mag = expf(Lre * dt);
    float th  = Lim * dt;
    float dar = mag * cosf(th);
    float dai = mag * sinf(th);
    float den = Lre * Lre + Lim * Lim;
    float nr = dar - 1.0f, ni = dai;
    float dbr = (nr * Lre + ni * Lim) / den;
    float dbi = (ni * Lre - nr * Lim) / den;
    g_ar[idx]  = dar; g_ai[idx] = dai;
    g_w2r[idx] = 2.0f * (Cre * dbr - Cim * dbi);
    g_w2i[idx] = 2.0f * (Cre * dbi + Cim * dbr);
    float prr = 1.0f, pii = 0.0f;
    size_t pb = (size_t)lh * TB * NN + (idx & 63);
    for (int t = 0; t < TB; ++t) {
        g_pr[pb + (size_t)t * NN] = prr;
        g_pi[pb + (size_t)t * NN] = pii;
        float tr = prr * dar - pii * dai;
        pii = prr * dai + pii * dar;
        prr = tr;
    }
    g_aTr[idx] = prr; g_aTi[idx] = pii;
}

// warp per (lh, d): lanes split n (2 each), shfl reduce
__global__ void kv_build(const float* __restrict__ dcoef) {
    int gw   = (blockIdx.x * blockDim.x + threadIdx.x) >> 5;
    int lane = threadIdx.x & 31;
    int d  = gw & 63;
    int lh = gw >> 6;
    const float* pr = &g_pr[((size_t)lh * TB + d) * NN];
    const float* pi = &g_pi[((size_t)lh * TB + d) * NN];
    const float* wr = &g_w2r[lh * NN];
    const float* wi = &g_w2i[lh * NN];
    float s = wr[lane] * pr[lane] - wi[lane] * pi[lane];
    s += wr[lane + 32] * pr[lane + 32] - wi[lane + 32] * pi[lane + 32];
    #pragma unroll
    for (int m = 16; m; m >>= 1) s += __shfl_xor_sync(0xffffffffu, s, m);
    if (lane == 0) {
        if (d == 0) s += dcoef[lh];
        g_kv[lh * TB + d] = s;
    }
}

// Merged tf32 pack of BOTH B matrices; one block per lh.
// Loads g_pr/g_pi (+kv) once into smem, emits g_bl and g_bc.
__global__ void pack_b() {
    __shared__ float spr[64][65];
    __shared__ float spi[64][65];
    __shared__ float skv[64];
    int lh  = blockIdx.x;
    int tid = threadIdx.x;
    const float* pr = &g_pr[(size_t)lh * TB * NN];
    const float* pi = &g_pi[(size_t)lh * TB * NN];
    for (int i = tid; i < 64 * 64; i += 256) {
        int t = i >> 6, n = i & 63;
        spr[t][n] = pr[i];
        spi[t][n] = pi[i];
    }
    if (tid < 64) skv[tid] = g_kv[lh * TB + tid];
    __syncthreads();
    // GEMM1 B: [s=64][n=192]
    uint32_t* bl = &g_bl[(size_t)lh * 64 * 192];
    for (int i = tid; i < 64 * 192; i += 256) {
        int n = i % 192, s = i / 192;
        float x;
        if (n < 64)        x = (n >= s) ? skv[n - s] : 0.0f;
        else if (n < 128)  x = spr[63 - s][n - 64];
        else               x = spi[63 - s][n - 128];
        bl[i] = f2tf32(x);
    }
    // GEMM2 B: [k=128][t=64]
    uint32_t* bc = &g_bc[(size_t)lh * 128 * 64];
    for (int i = tid; i < 128 * 64; i += 256) {
        int k = i >> 6, t = i & 63;
        float x = (k < 64) ? spr[t][k] : -spi[t][k - 64];
        bc[i] = f2tf32(x);
    }
}

// ------------------------------------------------------------------
// Fused SSM block-conv kernel, tf32 tensor cores (R15 version).
// ------------------------------------------------------------------
#define SM_ER  (64 * 68)
#define SM_EI  (2 * 64 * 68)
#define SM_ST  (3 * 64 * 68)
#define ST_A   0
#define ST_B   (16 * 72)
#define SSM_SMEM ((3 * 64 * 68 + 16 * 72 + 16 * 200) * 4)

__global__ void __launch_bounds__(256) ssm_conv(int li) {
    extern __shared__ float smf[];
    float* Ys = smf;
    float* Er = smf + SM_ER;
    float* Ei = smf + SM_EI;
    uint32_t* stg = reinterpret_cast<uint32_t*>(smf + SM_ST);
    uint32_t* As = stg + ST_A;
    uint32_t* Bs = stg + ST_B;

    int tid  = threadIdx.x;
    int wid  = tid >> 5;
    int lane = tid & 31;
    int g    = lane >> 2;
    int t4   = lane & 3;
    int bx   = blockIdx.x;
    int h    = blockIdx.y;
    int lh   = li * HH + h;
    int b0   = bx * 2;

    const size_t zb0 = ((size_t)(b0 * HH + h)) * LL;
    const size_t zb1 = ((size_t)((b0 + 1) * HH + h)) * LL;

    // ---- Phase 1: [Y | Er | Ei] = Z @ Bl  (64m x 192n, K=64, tf32) ----
    int wm = wid & 1;
    int wn = wid >> 1;
    float acc[2][6][4];
    #pragma unroll
    for (int mi = 0; mi < 2; ++mi)
        #pragma unroll
        for (int nj = 0; nj < 6; ++nj)
            #pragma unroll
            for (int r = 0; r < 4; ++r) acc[mi][nj][r] = 0.0f;

    for (int c = 0; c < 4; ++c) {
        __syncthreads();
        {
            int m = tid & 63, q = tid >> 6;
            size_t zb = (m < 32) ? zb0 : zb1;
            int blk = m & 31;
            const float* src = g_zt + zb + blk * TB + c * 16 + q * 4;
            float4 v = *reinterpret_cast<const float4*>(src);
            As[(q*4+0)*72 + m] = f2tf32(v.x);
            As[(q*4+1)*72 + m] = f2tf32(v.y);
            As[(q*4+2)*72 + m] = f2tf32(v.z);
            As[(q*4+3)*72 + m] = f2tf32(v.w);
        }
        {
            int krow = tid >> 4, nb = tid & 15;
            size_t bb = ((size_t)lh * 64 + c * 16 + krow) * 192;
            #pragma unroll
            for (int j = 0; j < 12; ++j) {
                int n = nb + 16 * j;
                Bs[krow * 200 + n] = g_bl[bb + n];
            }
        }
        __syncthreads();
        #pragma unroll
        for (int ks = 0; ks < 2; ++ks) {
            int kb = ks * 8;
            #pragma unroll
            for (int mi = 0; mi < 2; ++mi) {
                int mr = wm * 32 + mi * 16 + g;
                uint32_t a0 = As[(kb + t4)     * 72 + mr];
                uint32_t a1 = As[(kb + t4)     * 72 + mr + 8];
                uint32_t a2 = As[(kb + t4 + 4) * 72 + mr];
                uint32_t a3 = As[(kb + t4 + 4) * 72 + mr + 8];
                #pragma unroll
                for (int nj = 0; nj < 6; ++nj) {
                    int nc = wn * 48 + nj * 8 + g;
                    uint32_t b0 = Bs[(kb + t4)     * 200 + nc];
                    uint32_t b1 = Bs[(kb + t4 + 4) * 200 + nc];
                    mma_tf32(acc[mi][nj], a0, a1, a2, a3, b0, b1);
                }
            }
        }
    }
    __syncthreads();
    #pragma unroll
    for (int mi = 0; mi < 2; ++mi) {
        #pragma unroll
        for (int nj = 0; nj < 6; ++nj) {
            int gn = wn * 48 + nj * 8;
            int colp = gn + t4 * 2;
            float* dst; int cc;
            if (gn < 64)       { dst = Ys; cc = colp; }
            else if (gn < 128) { dst = Er; cc = colp - 64; }
            else               { dst = Ei; cc = colp - 128; }
            int r = wm * 32 + mi * 16 + g;
            dst[r * 68 + cc]       = acc[mi][nj][0];
            dst[r * 68 + cc + 1]   = acc[mi][nj][1];
            dst[(r+8) * 68 + cc]   = acc[mi][nj][2];
            dst[(r+8) * 68 + cc+1] = acc[mi][nj][3];
        }
    }
    __syncthreads();

    // ---- Phase 2: block scan, Er/Ei -> U (in place) ----
    if (tid < 128) {
        int bl = tid >> 6;
        int n  = tid & 63;
        int pidx = lh * NN + n;
        float dar = g_ar[pidx],  dai = g_ai[pidx];
        float aTr = g_aTr[pidx], aTi = g_aTi[pidx];
        float w2r = g_w2r[pidx], w2i = g_w2i[pidx];
        float wdr = w2r * dar - w2i * dai;
        float wdi = w2r * dai + w2i * dar;
        float Sr = 0.f, Si = 0.f, epr = 0.f, epi = 0.f;
        for (int blk = 0; blk < NBLK; ++blk) {
            int row = bl * 32 + blk;
            float er = Er[row * 68 + n];
            float ei = Ei[row * 68 + n];
            float ur = 0.f, ui = 0.f;
            if (blk > 0) {
                float nsr = aTr * Sr - aTi * Si + epr;
                float nsi = aTr * Si + aTi * Sr + epi;
                Sr = nsr; Si = nsi;
                ur = wdr * Sr - wdi * Si;
                ui = wdr * Si + wdi * Sr;
            }
            Er[row * 68 + n] = ur;
            Ei[row * 68 + n] = ui;
            epr = er; epi = ei;
        }
    }

    // ---- Phase 3: C = [Ur|Ui] @ Bc (64m x 64t, K=128, tf32) ----
    int wm2 = wid & 1;
    int wn2 = wid >> 1;
    float acc2[2][2][4];
    #pragma unroll
    for (int mi = 0; mi < 2; ++mi)
        #pragma unroll
        for (int nj = 0; nj < 2; ++nj)
            #pragma unroll
            for (int r = 0; r < 4; ++r) acc2[mi][nj][r] = 0.0f;

    for (int c = 0; c < 8; ++c) {
        __syncthreads();
        {
            int m = tid & 63, q = tid >> 6;
            int np = c * 16 + q * 4;
            const float* S = (np < 64) ? Er : Ei;
            int off = np & 63;
            As[(q*4+0)*72 + m] = f2tf32(S[m*68 + off+0]);
            As[(q*4+1)*72 + m] = f2tf32(S[m*68 + off+1]);
            As[(q*4+2)*72 + m] = f2tf32(S[m*68 + off+2]);
            As[(q*4+3)*72 + m] = f2tf32(S[m*68 + off+3]);
        }
        {
            int krow = tid >> 4, tb = tid & 15;
            size_t bb = ((size_t)lh * 128 + c * 16 + krow) * 64;
            #pragma unroll
            for (int j = 0; j < 4; ++j) {
                int tt = tb + 16 * j;
                Bs[krow * 72 + tt] = g_bc[bb + tt];
            }
        }
        __syncthreads();
        #pragma unroll
        for (int ks = 0; ks < 2; ++ks) {
            int kb = ks * 8;
            #pragma unroll
            for (int mi = 0; mi < 2; ++mi) {
                int mr = wm2 * 32 + mi * 16 + g;
                uint32_t a0 = As[(kb + t4)     * 72 + mr];
                uint32_t a1 = As[(kb + t4)     * 72 + mr + 8];
                uint32_t a2 = As[(kb + t4 + 4) * 72 + mr];
                uint32_t a3 = As[(kb + t4 + 4) * 72 + mr + 8];
                #pragma unroll
                for (int nj = 0; nj < 2; ++nj) {
                    int nc = wn2 * 16 + nj * 8 + g;
                    uint32_t b0 = Bs[(kb + t4)     * 72 + nc];
                    uint32_t b1 = Bs[(kb + t4 + 4) * 72 + nc];
                    mma_tf32(acc2[mi][nj], a0, a1, a2, a3, b0, b1);
                }
            }
        }
    }
    __syncthreads();
    #pragma unroll
    for (int mi = 0; mi < 2; ++mi) {
        #pragma unroll
        for (int nj = 0; nj < 2; ++nj) {
            int colp = wn2 * 16 + nj * 8 + t4 * 2;
            #pragma unroll
            for (int rr = 0; rr < 2; ++rr) {
                int r = wm2 * 32 + mi * 16 + g + rr * 8;
                float y0 = Ys[r * 68 + colp]     + acc2[mi][nj][rr*2+0];
                float y1 = Ys[r * 68 + colp + 1] + acc2[mi][nj][rr*2+1];
                y0 = gelu1(y0); y1 = gelu1(y1);
                int b  = b0 + (r >> 5);
                int blk = r & 31;
                float* dst = &g_yt[((size_t)(b * HH + h)) * LL + blk * TB + colp];
                *reinterpret_cast<float2*>(dst) = make_float2(y0, y1);
            }
        }
    }
}

// ------------------------------------------------------------------
// GLU GEMM, tf32, DOUBLE-BUFFERED smem staging (1 sync per k-chunk).
// ------------------------------------------------------------------
#define ASTR 136
#define BSTR 72
#define GLU_AS (32 * ASTR)
#define GLU_BS (32 * BSTR)
#define GLU_SMEM ((2 * GLU_AS + 4 * GLU_BS) * 4)

__global__ void __launch_bounds__(256) glu_gemm_mma(
        const float* __restrict__ W1, const float* __restrict__ W2,
        const float* __restrict__ b1, const float* __restrict__ b2) {
    extern __shared__ uint32_t gsm[];
    int tid  = threadIdx.x;
    int wid  = tid >> 5;
    int lane = tid & 31;
    int g    = lane >> 2;
    int t    = lane & 3;
    int wm   = wid & 3;
    int wn   = wid >> 2;
    int m0  = blockIdx.x * 128;
    int n0  = blockIdx.y * 64;
    int bch = m0 >> 11;
    int ml0 = m0 & 2047;

    float acc1[2][4][4];
    float acc2[2][4][4];
    #pragma unroll
    for (int mi = 0; mi < 2; ++mi)
        #pragma unroll
        for (int nj = 0; nj < 4; ++nj)
            #pragma unroll
            for (int r = 0; r < 4; ++r) { acc1[mi][nj][r] = 0.f; acc2[mi][nj][r] = 0.f; }

    for (int cc8 = 0; cc8 < 8; ++cc8) {
        int kc  = cc8 * 32;
        int buf = cc8 & 1;
        uint32_t* As  = gsm + buf * GLU_AS;
        uint32_t* Bs1 = gsm + 2 * GLU_AS + buf * GLU_BS;
        uint32_t* Bs2 = gsm + 2 * GLU_AS + 2 * GLU_BS + buf * GLU_BS;
        #pragma unroll
        for (int it = 0; it < 4; ++it) {
            int item = it * 256 + tid;
            int krow = item >> 5;
            int c4   = (item & 31) * 4;
            const float* src = &g_yt[(size_t)(bch * HH + kc + krow) * LL + ml0 + c4];
            float4 v = *reinterpret_cast<const float4*>(src);
            uint32_t* dst = &As[krow * ASTR + c4];
            asm volatile("st.shared.v4.b32 [%0], {%1,%2,%3,%4};"
                :: "l"(dst), "r"(f2tf32(v.x)), "r"(f2tf32(v.y)),
                   "r"(f2tf32(v.z)), "r"(f2tf32(v.w)) : "memory");
        }
        #pragma unroll
        for (int it = 0; it < 2; ++it) {
            int item = it * 256 + tid;
            int gg = item & 63;
            int kq = item >> 6;
            size_t off = (size_t)(n0 + gg) * HH + kc + kq * 4;
            float4 w1 = *reinterpret_cast<const float4*>(&W1[off]);
            float4 w2 = *reinterpret_cast<const float4*>(&W2[off]);
            int kb = kq * 4;
            Bs1[(kb+0) * BSTR + gg] = f2tf32(w1.x);
            Bs1[(kb+1) * BSTR + gg] = f2tf32(w1.y);
            Bs1[(kb+2) * BSTR + gg] = f2tf32(w1.z);
            Bs1[(kb+3) * BSTR + gg] = f2tf32(w1.w);
            Bs2[(kb+0) * BSTR + gg] = f2tf32(w2.x);
            Bs2[(kb+1) * BSTR + gg] = f2tf32(w2.y);
            Bs2[(kb+2) * BSTR + gg] = f2tf32(w2.z);
            Bs2[(kb+3) * BSTR + gg] = f2tf32(w2.w);
        }
        __syncthreads();
        #pragma unroll
        for (int ks = 0; ks < 4; ++ks) {
            int kb = ks * 8;
            uint32_t af[2][4];
            #pragma unroll
            for (int mi = 0; mi < 2; ++mi) {
                int mrow = wm * 32 + mi * 16;
                af[mi][0] = As[(kb + t)     * ASTR + mrow + g];
                af[mi][1] = As[(kb + t)     * ASTR + mrow + g + 8];
                af[mi][2] = As[(kb + t + 4) * ASTR + mrow + g];
                af[mi][3] = As[(kb + t + 4) * ASTR + mrow + g + 8];
            }
            #pragma unroll
            for (int nj = 0; nj < 4; ++nj) {
                int ncol = wn * 32 + nj * 8 + g;
                uint32_t bA0 = Bs1[(kb + t)     * BSTR + ncol];
                uint32_t bA1 = Bs1[(kb + t + 4) * BSTR + ncol];
                uint32_t bB0 = Bs2[(kb + t)     * BSTR + ncol];
                uint32_t bB1 = Bs2[(kb + t + 4) * BSTR + ncol];
                #pragma unroll
                for (int mi = 0; mi < 2; ++mi) {
                    mma_tf32(acc1[mi][nj], af[mi][0], af[mi][1], af[mi][2], af[mi][3], bA0, bA1);
                    mma_tf32(acc2[mi][nj], af[mi][0], af[mi][1], af[mi][2], af[mi][3], bB0, bB1);
                }
            }
        }
    }
    #pragma unroll
    for (int nj = 0; nj < 4; ++nj) {
        int ncol = n0 + wn * 32 + nj * 8 + t * 2;
        float bb1a = b1[ncol], bb1b = b1[ncol + 1];
        float bb2a = b2[ncol], bb2b = b2[ncol + 1];
        #pragma unroll
        for (int mi = 0; mi < 2; ++mi) {
            #pragma unroll
            for (int rr = 0; rr < 2; ++rr) {
                int mrow = m0 + wm * 32 + mi * 16 + g + rr * 8;
                float* hp = &g_h[(size_t)mrow * HH + ncol];
                float2 hv = *reinterpret_cast<float2*>(hp);
                float d1a = acc1[mi][nj][rr * 2 + 0] + bb1a;
                float d1b = acc1[mi][nj][rr * 2 + 1] + bb1b;
                float d2a = acc2[mi][nj][rr * 2 + 0] + bb2a;
                float d2b = acc2[mi][nj][rr * 2 + 1] + bb2b;
                hv.x += d1a * (1.0f / (1.0f + expf(-d2a)));
                hv.y += d1b * (1.0f / (1.0f + expf(-d2b)));
                *reinterpret_cast<float2*>(hp) = hv;
            }
        }
    }
}

__global__ void dec_kernel(const float* __restrict__ dw,
                           const float* __restrict__ db,
                           float* __restrict__ out) {
    int warp = (blockIdx.x * blockDim.x + threadIdx.x) >> 5;
    int lane = threadIdx.x & 31;
    const float* row = g_h + (size_t)warp * HH;
    float hr[8];
    #pragma unroll
    for (int k = 0; k < 8; ++k) hr[k] = row[lane + 32 * k];
    for (int o = 0; o < OUTD; ++o) {
        const float* wrow = dw + o * HH + lane;
        float acc = 0.0f;
        #pragma unroll
        for (int k = 0; k < 8; ++k) acc = fmaf(hr[k], wrow[32 * k], acc);
        #pragma unroll
        for (int m = 16; m; m >>= 1) acc += __shfl_xor_sync(0xffffffffu, acc, m);
        if (lane == 0) out[(size_t)warp * OUTD + o] = acc + db[o];
    }
}

extern "C" void kernel_launch(void* const* d_in, const int* in_sizes, int n_in,
                              void* d_out, int out_size) {
    const float* x     = (const float*)d_in[0];
    const float* enc_w = (const float*)d_in[1];
    const float* enc_b = (const float*)d_in[2];
    const float* lre   = (const float*)d_in[3];
    const float* lim   = (const float*)d_in[4];
    const float* cre   = (const float*)d_in[5];
    const float* cim   = (const float*)d_in[6];
    const float* dd    = (const float*)d_in[7];
    const float* lstep = (const float*)d_in[8];
    const float* lns   = (const float*)d_in[9];
    const float* lnb   = (const float*)d_in[10];
    const float* ow    = (const float*)d_in[11];
    const float* ob    = (const float*)d_in[12];
    const float* o2w   = (const float*)d_in[13];
    const float* o2b   = (const float*)d_in[14];
    const float* dw    = (const float*)d_in[15];
    const float* db    = (const float*)d_in[16];
    float* out = (float*)d_out;

    cudaFuncSetAttribute(ssm_conv,
                         cudaFuncAttributeMaxDynamicSharedMemorySize, SSM_SMEM);
    cudaFuncSetAttribute(glu_gemm_mma,
                         cudaFuncAttributeMaxDynamicSharedMemorySize, GLU_SMEM);

    ssm_prep<<<(LH * NN) / 256, 256>>>(lre, lim, cre, cim, lstep);
    kv_build<<<(LH * TB * 32) / 256, 256>>>(dd);
    pack_b<<<LH, 256>>>();

    enc_kernel<<<(BB * LL) / 16, 256>>>(x, enc_w, enc_b);

    for (int li = 0; li < NLAY; ++li) {
        ln_kernel<<<(BB * LL) / 32, 256>>>(lns + li * HH, lnb + li * HH);
        ssm_conv<<<dim3(8, HH), 256, SSM_SMEM>>>(li);
        glu_gemm_mma<<<dim3((BB * LL) / 128, HH / 64), 256, GLU_SMEM>>>(
            ow + li * HH * HH, o2w + li * HH * HH,
            ob + li * HH, o2b + li * HH);
    }

    dec_kernel<<<(BB * LL) / 8, 256>>>(dw, db, out);
}

// round 17
// speedup vs baseline: 1.0440x; 1.0440x over previous
#include <cuda_runtime.h>
#include <cuda_bf16.h>
#include <math.h>
#include <stdint.h>

#define BB   16
#define LL   2048
#define HH   256
#define NN   64
#define NLAY 4
#define IND  40
#define OUTD 33
#define TB   64
#define NBLK 32
#define LH   (NLAY * HH)

typedef unsigned long long ull;

__device__ float g_h [BB * LL * HH];
__device__ float g_zt[BB * HH * LL];
__device__ float g_yt[BB * HH * LL];
__device__ float g_ar [LH * NN], g_ai [LH * NN];
__device__ float g_w2r[LH * NN], g_w2i[LH * NN];
__device__ float g_aTr[LH * NN], g_aTi[LH * NN];
__device__ float g_pr [LH * TB * NN], g_pi [LH * TB * NN];
__device__ float g_kv [LH * TB];
__device__ uint32_t g_bl[LH * 64 * 192];   // tf32 B for GEMM1 [lh][k=64][n=192]
__device__ uint32_t g_bc[LH * 128 * 64];   // tf32 B for GEMM2 [lh][k=128][t=64]

__device__ __forceinline__ float gelu1(float x) {
    const float c0 = 0.7978845608028654f, c1 = 0.044715f;
    float t = tanhf(c0 * (x + c1 * x * x * x));
    return 0.5f * x * (1.0f + t);
}
__device__ __forceinline__ uint32_t f2tf32(float x) {
    uint32_t r; asm("cvt.rna.tf32.f32 %0, %1;" : "=r"(r) : "f"(x)); return r;
}
__device__ __forceinline__ void mma_tf32(float c[4], uint32_t a0, uint32_t a1,
                                         uint32_t a2, uint32_t a3,
                                         uint32_t b0, uint32_t b1) {
    asm volatile("mma.sync.aligned.m16n8k8.row.col.f32.tf32.tf32.f32 "
        "{%0,%1,%2,%3}, {%4,%5,%6,%7}, {%8,%9}, {%0,%1,%2,%3};"
        : "+f"(c[0]), "+f"(c[1]), "+f"(c[2]), "+f"(c[3])
        : "r"(a0), "r"(a1), "r"(a2), "r"(a3), "r"(b0), "r"(b1));
}

// Encoder: weights hoisted to registers (1 LDS/FFMA inner loop).
__global__ void enc_kernel(const float* __restrict__ x,
                           const float* __restrict__ ew,
                           const float* __restrict__ eb) {
    __shared__ float sw[IND * HH];
    __shared__ float sx[16 * IND];
    int tid = threadIdx.x;
    for (int idx = tid; idx < HH * IND; idx += 256) {
        int h = idx / IND, i = idx % IND;
        sw[i * HH + h] = ew[idx];
    }
    int m0 = blockIdx.x * 16;
    for (int idx = tid; idx < 16 * IND; idx += 256)
        sx[idx] = x[(size_t)m0 * IND + idx];
    __syncthreads();
    float w[IND];
    #pragma unroll
    for (int i = 0; i < IND; ++i) w[i] = sw[i * HH + tid];
    float bias = eb[tid];
    for (int r = 0; r < 16; ++r) {
        float acc = bias;
        #pragma unroll
        for (int i = 0; i < IND; ++i)
            acc = fmaf(sx[r * IND + i], w[i], acc);
        g_h[(size_t)(m0 + r) * HH + tid] = acc;
    }
}

__global__ void ln_kernel(const float* __restrict__ sc,
                          const float* __restrict__ bi) {
    __shared__ float sm[32][257];
    int tid  = threadIdx.x;
    int warp = tid >> 5;
    int lane = tid & 31;
    int m0 = blockIdx.x * 32;
    for (int r = warp; r < 32; r += 8) {
        const float* row = g_h + (size_t)(m0 + r) * HH;
        float4 v0 = *reinterpret_cast<const float4*>(row + lane * 4);
        float4 v1 = *reinterpret_cast<const float4*>(row + 128 + lane * 4);
        float s = v0.x + v0.y + v0.z + v0.w + v1.x + v1.y + v1.z + v1.w;
        float q = v0.x*v0.x + v0.y*v0.y + v0.z*v0.z + v0.w*v0.w
                + v1.x*v1.x + v1.y*v1.y + v1.z*v1.z + v1.w*v1.w;
        #pragma unroll
        for (int m = 16; m; m >>= 1) {
            s += __shfl_xor_sync(0xffffffffu, s, m);
            q += __shfl_xor_sync(0xffffffffu, q, m);
        }
        float mu  = s * (1.0f / 256.0f);
        float var = q * (1.0f / 256.0f) - mu * mu;
        float inv = rsqrtf(var + 1e-5f);
        int h0 = lane * 4, h1 = 128 + lane * 4;
        sm[r][h0+0] = (v0.x - mu) * inv * sc[h0+0] + bi[h0+0];
        sm[r][h0+1] = (v0.y - mu) * inv * sc[h0+1] + bi[h0+1];
        sm[r][h0+2] = (v0.z - mu) * inv * sc[h0+2] + bi[h0+2];
        sm[r][h0+3] = (v0.w - mu) * inv * sc[h0+3] + bi[h0+3];
        sm[r][h1+0] = (v1.x - mu) * inv * sc[h1+0] + bi[h1+0];
        sm[r][h1+1] = (v1.y - mu) * inv * sc[h1+1] + bi[h1+1];
        sm[r][h1+2] = (v1.z - mu) * inv * sc[h1+2] + bi[h1+2];
        sm[r][h1+3] = (v1.w - mu) * inv * sc[h1+3] + bi[h1+3];
    }
    __syncthreads();
    int b  = m0 >> 11;
    int l0 = m0 & 2047;
    for (int h = warp; h < HH; h += 8)
        g_zt[((size_t)(b * HH + h)) * LL + l0 + lane] = sm[lane][h];
}

// ------------------------------------------------------------------
// Batched (all-layer) parameter pipeline
// ------------------------------------------------------------------
__global__ void ssm_prep(const float* __restrict__ lre,
                         const float* __restrict__ lim,
                         const float* __restrict__ cre,
                         const float* __restrict__ cim,
                         const float* __restrict__ lstep) {
    int idx = blockIdx.x * blockDim.x + threadIdx.x;   // over LH*NN
    int lh = idx >> 6;
    float Lre = lre[idx], Lim = lim[idx];
    float Cre = cre[idx], Cim = cim[idx];
    float dt  = expf(lstep[lh]);
    float mag = expf(Lre * dt);
    float th  = Lim * dt;
    float dar = mag * cosf(th);
    float dai = mag * sinf(th);
    float den = Lre * Lre + Lim * Lim;
    float nr = dar - 1.0f, ni = dai;
    float dbr = (nr * Lre + ni * Lim) / den;
    float dbi = (ni * Lre - nr * Lim) / den;
    g_ar[idx]  = dar; g_ai[idx] = dai;
    g_w2r[idx] = 2.0f * (Cre * dbr - Cim * dbi);
    g_w2i[idx] = 2.0f * (Cre * dbi + Cim * dbr);
    float prr = 1.0f, pii = 0.0f;
    size_t pb = (size_t)lh * TB * NN + (idx & 63);
    for (int t = 0; t < TB; ++t) {
        g_pr[pb + (size_t)t * NN] = prr;
        g_pi[pb + (size_t)t * NN] = pii;
        float tr = prr * dar - pii * dai;
        pii = prr * dai + pii * dar;
        prr = tr;
    }
    g_aTr[idx] = prr; g_aTi[idx] = pii;
}

// warp per (lh, d): lanes split n (2 each), shfl reduce
__global__ void kv_build(const float* __restrict__ dcoef) {
    int gw   = (blockIdx.x * blockDim.x + threadIdx.x) >> 5;
    int lane = threadIdx.x & 31;
    int d  = gw & 63;
    int lh = gw >> 6;
    const float* pr = &g_pr[((size_t)lh * TB + d) * NN];
    const float* pi = &g_pi[((size_t)lh * TB + d) * NN];
    const float* wr = &g_w2r[lh * NN];
    const float* wi = &g_w2i[lh * NN];
    float s = wr[lane] * pr[lane] - wi[lane] * pi[lane];
    s += wr[lane + 32] * pr[lane + 32] - wi[lane + 32] * pi[lane + 32];
    #pragma unroll
    for (int m = 16; m; m >>= 1) s += __shfl_xor_sync(0xffffffffu, s, m);
    if (lane == 0) {
        if (d == 0) s += dcoef[lh];
        g_kv[lh * TB + d] = s;
    }
}

// Merged tf32 pack of BOTH B matrices; one block per lh.
__global__ void pack_b() {
    __shared__ float spr[64][65];
    __shared__ float spi[64][65];
    __shared__ float skv[64];
    int lh  = blockIdx.x;
    int tid = threadIdx.x;
    const float* pr = &g_pr[(size_t)lh * TB * NN];
    const float* pi = &g_pi[(size_t)lh * TB * NN];
    for (int i = tid; i < 64 * 64; i += 256) {
        int t = i >> 6, n = i & 63;
        spr[t][n] = pr[i];
        spi[t][n] = pi[i];
    }
    if (tid < 64) skv[tid] = g_kv[lh * TB + tid];
    __syncthreads();
    uint32_t* bl = &g_bl[(size_t)lh * 64 * 192];
    for (int i = tid; i < 64 * 192; i += 256) {
        int n = i % 192, s = i / 192;
        float x;
        if (n < 64)        x = (n >= s) ? skv[n - s] : 0.0f;
        else if (n < 128)  x = spr[63 - s][n - 64];
        else               x = spi[63 - s][n - 128];
        bl[i] = f2tf32(x);
    }
    uint32_t* bc = &g_bc[(size_t)lh * 128 * 64];
    for (int i = tid; i < 128 * 64; i += 256) {
        int k = i >> 6, t = i & 63;
        float x = (k < 64) ? spr[t][k] : -spi[t][k - 64];
        bc[i] = f2tf32(x);
    }
}

// ------------------------------------------------------------------
// Fused SSM block-conv kernel, tf32 tensor cores (R15 version).
// ------------------------------------------------------------------
#define SM_ER  (64 * 68)
#define SM_EI  (2 * 64 * 68)
#define SM_ST  (3 * 64 * 68)
#define ST_A   0
#define ST_B   (16 * 72)
#define SSM_SMEM ((3 * 64 * 68 + 16 * 72 + 16 * 200) * 4)

__global__ void __launch_bounds__(256) ssm_conv(int li) {
    extern __shared__ float smf[];
    float* Ys = smf;
    float* Er = smf + SM_ER;
    float* Ei = smf + SM_EI;
    uint32_t* stg = reinterpret_cast<uint32_t*>(smf + SM_ST);
    uint32_t* As = stg + ST_A;
    uint32_t* Bs = stg + ST_B;

    int tid  = threadIdx.x;
    int wid  = tid >> 5;
    int lane = tid & 31;
    int g    = lane >> 2;
    int t4   = lane & 3;
    int bx   = blockIdx.x;
    int h    = blockIdx.y;
    int lh   = li * HH + h;
    int b0   = bx * 2;

    const size_t zb0 = ((size_t)(b0 * HH + h)) * LL;
    const size_t zb1 = ((size_t)((b0 + 1) * HH + h)) * LL;

    int wm = wid & 1;
    int wn = wid >> 1;
    float acc[2][6][4];
    #pragma unroll
    for (int mi = 0; mi < 2; ++mi)
        #pragma unroll
        for (int nj = 0; nj < 6; ++nj)
            #pragma unroll
            for (int r = 0; r < 4; ++r) acc[mi][nj][r] = 0.0f;

    for (int c = 0; c < 4; ++c) {
        __syncthreads();
        {
            int m = tid & 63, q = tid >> 6;
            size_t zb = (m < 32) ? zb0 : zb1;
            int blk = m & 31;
            const float* src = g_zt + zb + blk * TB + c * 16 + q * 4;
            float4 v = *reinterpret_cast<const float4*>(src);
            As[(q*4+0)*72 + m] = f2tf32(v.x);
            As[(q*4+1)*72 + m] = f2tf32(v.y);
            As[(q*4+2)*72 + m] = f2tf32(v.z);
            As[(q*4+3)*72 + m] = f2tf32(v.w);
        }
        {
            int krow = tid >> 4, nb = tid & 15;
            size_t bb = ((size_t)lh * 64 + c * 16 + krow) * 192;
            #pragma unroll
            for (int j = 0; j < 12; ++j) {
                int n = nb + 16 * j;
                Bs[krow * 200 + n] = g_bl[bb + n];
            }
        }
        __syncthreads();
        #pragma unroll
        for (int ks = 0; ks < 2; ++ks) {
            int kb = ks * 8;
            #pragma unroll
            for (int mi = 0; mi < 2; ++mi) {
                int mr = wm * 32 + mi * 16 + g;
                uint32_t a0 = As[(kb + t4)     * 72 + mr];
                uint32_t a1 = As[(kb + t4)     * 72 + mr + 8];
                uint32_t a2 = As[(kb + t4 + 4) * 72 + mr];
                uint32_t a3 = As[(kb + t4 + 4) * 72 + mr + 8];
                #pragma unroll
                for (int nj = 0; nj < 6; ++nj) {
                    int nc = wn * 48 + nj * 8 + g;
                    uint32_t b0 = Bs[(kb + t4)     * 200 + nc];
                    uint32_t b1 = Bs[(kb + t4 + 4) * 200 + nc];
                    mma_tf32(acc[mi][nj], a0, a1, a2, a3, b0, b1);
                }
            }
        }
    }
    __syncthreads();
    #pragma unroll
    for (int mi = 0; mi < 2; ++mi) {
        #pragma unroll
        for (int nj = 0; nj < 6; ++nj) {
            int gn = wn * 48 + nj * 8;
            int colp = gn + t4 * 2;
            float* dst; int cc;
            if (gn < 64)       { dst = Ys; cc = colp; }
            else if (gn < 128) { dst = Er; cc = colp - 64; }
            else               { dst = Ei; cc = colp - 128; }
            int r = wm * 32 + mi * 16 + g;
            dst[r * 68 + cc]       = acc[mi][nj][0];
            dst[r * 68 + cc + 1]   = acc[mi][nj][1];
            dst[(r+8) * 68 + cc]   = acc[mi][nj][2];
            dst[(r+8) * 68 + cc+1] = acc[mi][nj][3];
        }
    }
    __syncthreads();

    if (tid < 128) {
        int bl = tid >> 6;
        int n  = tid & 63;
        int pidx = lh * NN + n;
        float dar = g_ar[pidx],  dai = g_ai[pidx];
        float aTr = g_aTr[pidx], aTi = g_aTi[pidx];
        float w2r = g_w2r[pidx], w2i = g_w2i[pidx];
        float wdr = w2r * dar - w2i * dai;
        float wdi = w2r * dai + w2i * dar;
        float Sr = 0.f, Si = 0.f, epr = 0.f, epi = 0.f;
        for (int blk = 0; blk < NBLK; ++blk) {
            int row = bl * 32 + blk;
            float er = Er[row * 68 + n];
            float ei = Ei[row * 68 + n];
            float ur = 0.f, ui = 0.f;
            if (blk > 0) {
                float nsr = aTr * Sr - aTi * Si + epr;
                float nsi = aTr * Si + aTi * Sr + epi;
                Sr = nsr; Si = nsi;
                ur = wdr * Sr - wdi * Si;
                ui = wdr * Si + wdi * Sr;
            }
            Er[row * 68 + n] = ur;
            Ei[row * 68 + n] = ui;
            epr = er; epi = ei;
        }
    }

    int wm2 = wid & 1;
    int wn2 = wid >> 1;
    float acc2[2][2][4];
    #pragma unroll
    for (int mi = 0; mi < 2; ++mi)
        #pragma unroll
        for (int nj = 0; nj < 2; ++nj)
            #pragma unroll
            for (int r = 0; r < 4; ++r) acc2[mi][nj][r] = 0.0f;

    for (int c = 0; c < 8; ++c) {
        __syncthreads();
        {
            int m = tid & 63, q = tid >> 6;
            int np = c * 16 + q * 4;
            const float* S = (np < 64) ? Er : Ei;
            int off = np & 63;
            As[(q*4+0)*72 + m] = f2tf32(S[m*68 + off+0]);
            As[(q*4+1)*72 + m] = f2tf32(S[m*68 + off+1]);
            As[(q*4+2)*72 + m] = f2tf32(S[m*68 + off+2]);
            As[(q*4+3)*72 + m] = f2tf32(S[m*68 + off+3]);
        }
        {
            int krow = tid >> 4, tb = tid & 15;
            size_t bb = ((size_t)lh * 128 + c * 16 + krow) * 64;
            #pragma unroll
            for (int j = 0; j < 4; ++j) {
                int tt = tb + 16 * j;
                Bs[krow * 72 + tt] = g_bc[bb + tt];
            }
        }
        __syncthreads();
        #pragma unroll
        for (int ks = 0; ks < 2; ++ks) {
            int kb = ks * 8;
            #pragma unroll
            for (int mi = 0; mi < 2; ++mi) {
                int mr = wm2 * 32 + mi * 16 + g;
                uint32_t a0 = As[(kb + t4)     * 72 + mr];
                uint32_t a1 = As[(kb + t4)     * 72 + mr + 8];
                uint32_t a2 = As[(kb + t4 + 4) * 72 + mr];
                uint32_t a3 = As[(kb + t4 + 4) * 72 + mr + 8];
                #pragma unroll
                for (int nj = 0; nj < 2; ++nj) {
                    int nc = wn2 * 16 + nj * 8 + g;
                    uint32_t b0 = Bs[(kb + t4)     * 72 + nc];
                    uint32_t b1 = Bs[(kb + t4 + 4) * 72 + nc];
                    mma_tf32(acc2[mi][nj], a0, a1, a2, a3, b0, b1);
                }
            }
        }
    }
    __syncthreads();
    #pragma unroll
    for (int mi = 0; mi < 2; ++mi) {
        #pragma unroll
        for (int nj = 0; nj < 2; ++nj) {
            int colp = wn2 * 16 + nj * 8 + t4 * 2;
            #pragma unroll
            for (int rr = 0; rr < 2; ++rr) {
                int r = wm2 * 32 + mi * 16 + g + rr * 8;
                float y0 = Ys[r * 68 + colp]     + acc2[mi][nj][rr*2+0];
                float y1 = Ys[r * 68 + colp + 1] + acc2[mi][nj][rr*2+1];
                y0 = gelu1(y0); y1 = gelu1(y1);
                int b  = b0 + (r >> 5);
                int blk = r & 31;
                float* dst = &g_yt[((size_t)(b * HH + h)) * LL + blk * TB + colp];
                *reinterpret_cast<float2*>(dst) = make_float2(y0, y1);
            }
        }
    }
}

// ------------------------------------------------------------------
// GLU GEMM, tf32 (R15 single-buffer version).
// ------------------------------------------------------------------
#define ASTR 136
#define BSTR 72
__global__ void __launch_bounds__(256) glu_gemm_mma(
        const float* __restrict__ W1, const float* __restrict__ W2,
        const float* __restrict__ b1, const float* __restrict__ b2) {
    __shared__ uint32_t As [32 * ASTR];
    __shared__ uint32_t Bs1[32 * BSTR];
    __shared__ uint32_t Bs2[32 * BSTR];
    int tid  = threadIdx.x;
    int wid  = tid >> 5;
    int lane = tid & 31;
    int g    = lane >> 2;
    int t    = lane & 3;
    int wm   = wid & 3;
    int wn   = wid >> 2;
    int m0  = blockIdx.x * 128;
    int n0  = blockIdx.y * 64;
    int bch = m0 >> 11;
    int ml0 = m0 & 2047;

    float acc1[2][4][4];
    float acc2[2][4][4];
    #pragma unroll
    for (int mi = 0; mi < 2; ++mi)
        #pragma unroll
        for (int nj = 0; nj < 4; ++nj)
            #pragma unroll
            for (int r = 0; r < 4; ++r) { acc1[mi][nj][r] = 0.f; acc2[mi][nj][r] = 0.f; }

    for (int kc = 0; kc < HH; kc += 32) {
        __syncthreads();
        #pragma unroll
        for (int it = 0; it < 4; ++it) {
            int item = it * 256 + tid;
            int krow = item >> 5;
            int c4   = (item & 31) * 4;
            const float* src = &g_yt[(size_t)(bch * HH + kc + krow) * LL + ml0 + c4];
            float4 v = *reinterpret_cast<const float4*>(src);
            uint32_t* dst = &As[krow * ASTR + c4];
            asm volatile("st.shared.v4.b32 [%0], {%1,%2,%3,%4};"
                :: "l"(dst), "r"(f2tf32(v.x)), "r"(f2tf32(v.y)),
                   "r"(f2tf32(v.z)), "r"(f2tf32(v.w)) : "memory");
        }
        #pragma unroll
        for (int it = 0; it < 2; ++it) {
            int item = it * 256 + tid;
            int gg = item & 63;
            int kq = item >> 6;
            size_t off = (size_t)(n0 + gg) * HH + kc + kq * 4;
            float4 w1 = *reinterpret_cast<const float4*>(&W1[off]);
            float4 w2 = *reinterpret_cast<const float4*>(&W2[off]);
            int kb = kq * 4;
            Bs1[(kb+0) * BSTR + gg] = f2tf32(w1.x);
            Bs1[(kb+1) * BSTR + gg] = f2tf32(w1.y);
            Bs1[(kb+2) * BSTR + gg] = f2tf32(w1.z);
            Bs1[(kb+3) * BSTR + gg] = f2tf32(w1.w);
            Bs2[(kb+0) * BSTR + gg] = f2tf32(w2.x);
            Bs2[(kb+1) * BSTR + gg] = f2tf32(w2.y);
            Bs2[(kb+2) * BSTR + gg] = f2tf32(w2.z);
            Bs2[(kb+3) * BSTR + gg] = f2tf32(w2.w);
        }
        __syncthreads();
        #pragma unroll
        for (int ks = 0; ks < 4; ++ks) {
            int kb = ks * 8;
            uint32_t af[2][4];
            #pragma unroll
            for (int mi = 0; mi < 2; ++mi) {
                int mrow = wm * 32 + mi * 16;
                af[mi][0] = As[(kb + t)     * ASTR + mrow + g];
                af[mi][1] = As[(kb + t)     * ASTR + mrow + g + 8];
                af[mi][2] = As[(kb + t + 4) * ASTR + mrow + g];
                af[mi][3] = As[(kb + t + 4) * ASTR + mrow + g + 8];
            }
            #pragma unroll
            for (int nj = 0; nj < 4; ++nj) {
                int ncol = wn * 32 + nj * 8 + g;
                uint32_t bA0 = Bs1[(kb + t)     * BSTR + ncol];
                uint32_t bA1 = Bs1[(kb + t + 4) * BSTR + ncol];
                uint32_t bB0 = Bs2[(kb + t)     * BSTR + ncol];
                uint32_t bB1 = Bs2[(kb + t + 4) * BSTR + ncol];
                #pragma unroll
                for (int mi = 0; mi < 2; ++mi) {
                    mma_tf32(acc1[mi][nj], af[mi][0], af[mi][1], af[mi][2], af[mi][3], bA0, bA1);
                    mma_tf32(acc2[mi][nj], af[mi][0], af[mi][1], af[mi][2], af[mi][3], bB0, bB1);
                }
            }
        }
    }
    #pragma unroll
    for (int nj = 0; nj < 4; ++nj) {
        int ncol = n0 + wn * 32 + nj * 8 + t * 2;
        float bb1a = b1[ncol], bb1b = b1[ncol + 1];
        float bb2a = b2[ncol], bb2b = b2[ncol + 1];
        #pragma unroll
        for (int mi = 0; mi < 2; ++mi) {
            #pragma unroll
            for (int rr = 0; rr < 2; ++rr) {
                int mrow = m0 + wm * 32 + mi * 16 + g + rr * 8;
                float* hp = &g_h[(size_t)mrow * HH + ncol];
                float2 hv = *reinterpret_cast<float2*>(hp);
                float d1a = acc1[mi][nj][rr * 2 + 0] + bb1a;
                float d1b = acc1[mi][nj][rr * 2 + 1] + bb1b;
                float d2a = acc2[mi][nj][rr * 2 + 0] + bb2a;
                float d2b = acc2[mi][nj][rr * 2 + 1] + bb2b;
                hv.x += d1a * (1.0f / (1.0f + expf(-d2a)));
                hv.y += d1b * (1.0f / (1.0f + expf(-d2b)));
                *reinterpret_cast<float2*>(hp) = hv;
            }
        }
    }
}

__global__ void dec_kernel(const float* __restrict__ dw,
                           const float* __restrict__ db,
                           float* __restrict__ out) {
    int warp = (blockIdx.x * blockDim.x + threadIdx.x) >> 5;
    int lane = threadIdx.x & 31;
    const float* row = g_h + (size_t)warp * HH;
    float hr[8];
    #pragma unroll
    for (int k = 0; k < 8; ++k) hr[k] = row[lane + 32 * k];
    for (int o = 0; o < OUTD; ++o) {
        const float* wrow = dw + o * HH + lane;
        float acc = 0.0f;
        #pragma unroll
        for (int k = 0; k < 8; ++k) acc = fmaf(hr[k], wrow[32 * k], acc);
        #pragma unroll
        for (int m = 16; m; m >>= 1) acc += __shfl_xor_sync(0xffffffffu, acc, m);
        if (lane == 0) out[(size_t)warp * OUTD + o] = acc + db[o];
    }
}

extern "C" void kernel_launch(void* const* d_in, const int* in_sizes, int n_in,
                              void* d_out, int out_size) {
    const float* x     = (const float*)d_in[0];
    const float* enc_w = (const float*)d_in[1];
    const float* enc_b = (const float*)d_in[2];
    const float* lre   = (const float*)d_in[3];
    const float* lim   = (const float*)d_in[4];
    const float* cre   = (const float*)d_in[5];
    const float* cim   = (const float*)d_in[6];
    const float* dd    = (const float*)d_in[7];
    const float* lstep = (const float*)d_in[8];
    const float* lns   = (const float*)d_in[9];
    const float* lnb   = (const float*)d_in[10];
    const float* ow    = (const float*)d_in[11];
    const float* ob    = (const float*)d_in[12];
    const float* o2w   = (const float*)d_in[13];
    const float* o2b   = (const float*)d_in[14];
    const float* dw    = (const float*)d_in[15];
    const float* db    = (const float*)d_in[16];
    float* out = (float*)d_out;

    cudaFuncSetAttribute(ssm_conv,
                         cudaFuncAttributeMaxDynamicSharedMemorySize, SSM_SMEM);

    ssm_prep<<<(LH * NN) / 256, 256>>>(lre, lim, cre, cim, lstep);
    kv_build<<<(LH * TB * 32) / 256, 256>>>(dd);
    pack_b<<<LH, 256>>>();

    enc_kernel<<<(BB * LL) / 16, 256>>>(x, enc_w, enc_b);

    for (int li = 0; li < NLAY; ++li) {
        ln_kernel<<<(BB * LL) / 32, 256>>>(lns + li * HH, lnb + li * HH);
        ssm_conv<<<dim3(8, HH), 256, SSM_SMEM>>>(li);
        glu_gemm_mma<<<dim3((BB * LL) / 128, HH / 64), 256>>>(
            ow + li * HH * HH, o2w + li * HH * HH,
            ob + li * HH, o2b + li * HH);
    }

    dec_kernel<<<(BB * LL) / 8, 256>>>(dw, db, out);
}